// round 3
// baseline (speedup 1.0000x reference)
#include <cuda_runtime.h>
#include <cuda_bf16.h>
#include <cstdint>

// out[784,65536] = relu( bcirc(W)[784,784] @ x[784,65536] + bias )
// mma.sync.m16n8k8.tf32 (sm_80+ PTX, no tcgen05 -- harness targets plain sm_103).
// CTA tile 128x128, BK=32, 8 warps (2m x 4n), double-buffered smem,
// cp.async for A, LDG+round+transpose STS for B.

#define BATCH   65536
#define K_PAD   800
#define BK      32
#define NCHUNK  25

#define A_BUF   16384            // 128 rows x 32 floats
#define B_STRIDE 36              // floats per n-row (32 + 4 pad), 144B
#define B_BUF   (128 * B_STRIDE * 4)   // 18432
#define SMEM_TOTAL (2 * A_BUF + 2 * B_BUF)   // 69632

__device__ float g_A[896 * K_PAD];   // bcirc(W), tf32-rounded, zero-padded

// ---------------- helpers ----------------
__device__ __forceinline__ uint32_t smem_u32(const void* p) {
    uint32_t a;
    asm("{ .reg .u64 t; cvta.to.shared.u64 t, %1; cvt.u32.u64 %0, t; }" : "=r"(a) : "l"(p));
    return a;
}
__device__ __forceinline__ float tf32_rn(float v) {
    uint32_t o;
    asm("cvt.rna.tf32.f32 %0, %1;" : "=r"(o) : "r"(__float_as_uint(v)));
    return __uint_as_float(o);
}
__device__ __forceinline__ void cp_async16(uint32_t dst, const void* src) {
    asm volatile("cp.async.cg.shared.global [%0], [%1], 16;" :: "r"(dst), "l"(src));
}
__device__ __forceinline__ void cp_async_wait_all() {
    asm volatile("cp.async.wait_all;" ::: "memory");
}
__device__ __forceinline__ void ldsm_x4(uint32_t& r0, uint32_t& r1, uint32_t& r2,
                                        uint32_t& r3, uint32_t addr) {
    asm volatile("ldmatrix.sync.aligned.m8n8.x4.shared.b16 {%0,%1,%2,%3}, [%4];"
                 : "=r"(r0), "=r"(r1), "=r"(r2), "=r"(r3) : "r"(addr));
}
__device__ __forceinline__ void sts128(uint32_t a, float x, float y, float z, float w) {
    asm volatile("st.shared.v4.b32 [%0], {%1, %2, %3, %4};"
                 :: "r"(a), "r"(__float_as_uint(x)), "r"(__float_as_uint(y)),
                    "r"(__float_as_uint(z)), "r"(__float_as_uint(w)));
}
__device__ __forceinline__ void mma_tf32(float* c, const uint32_t* a, const uint32_t* b) {
    asm volatile(
        "mma.sync.aligned.m16n8k8.row.col.f32.tf32.tf32.f32 "
        "{%0,%1,%2,%3}, {%4,%5,%6,%7}, {%8,%9}, {%0,%1,%2,%3};"
        : "+f"(c[0]), "+f"(c[1]), "+f"(c[2]), "+f"(c[3])
        : "r"(a[0]), "r"(a[1]), "r"(a[2]), "r"(a[3]), "r"(b[0]), "r"(b[1]));
}

// ---------------- prep: bcirc(W), tf32-rounded, zero-padded ----------------
__global__ void build_A_kernel(const float* __restrict__ W) {
    int idx = blockIdx.x * 256 + threadIdx.x;
    if (idx >= 896 * K_PAD) return;
    int r = idx / K_PAD, k = idx - r * K_PAD;
    float v = 0.0f;
    if (r < 784 && k < 784) {
        int ko = r / 28, m = r % 28, j = k / 28, n = k % 28;
        int l = ko - j; if (l < 0) l += 28;
        v = tf32_rn(W[l * 784 + m * 28 + n]);
    }
    g_A[idx] = v;
}

// ---------------- main GEMM ----------------
__global__ void __launch_bounds__(256)
tnn_gemm_kernel(float* __restrict__ out, const float* __restrict__ x,
                const float* __restrict__ bias) {
    extern __shared__ char smem[];
    const uint32_t sb = smem_u32(smem);
    const uint32_t aBase[2] = { sb, sb + A_BUF };
    const uint32_t bBase[2] = { sb + 2 * A_BUF, sb + 2 * A_BUF + B_BUF };

    const int tid    = threadIdx.x;
    const int lane   = tid & 31;
    const int wid    = tid >> 5;
    const int warp_m = wid & 1;          // 0..1 -> rows 0/64
    const int warp_n = wid >> 1;         // 0..3 -> cols 0/32/64/96
    const int bn0    = blockIdx.x * 128; // batch offset
    const int bm0    = blockIdx.y * 128; // row offset

    // ---- A cp.async mapping (4 x 16B per thread per chunk) ----
    // idx = i*256+tid; row = idx>>3; kq = idx&7; swizzled chunk pk = kq ^ (row&7)
    // ---- B LDG/STS mapping (4 x STS.128 per thread) ----
    // idx = i*256+tid; n = idx&127; kq = idx>>7; loads x[c*32+kq*4+j][bn0+n]

    auto load_A = [&](int c, int buf) {
        const float* src = g_A + (size_t)bm0 * K_PAD + c * BK;
        #pragma unroll
        for (int i = 0; i < 4; ++i) {
            int idx = i * 256 + tid;
            int row = idx >> 3, kq = idx & 7;
            int pk  = kq ^ (row & 7);
            cp_async16(aBase[buf] + row * 128 + pk * 16,
                       src + (size_t)row * K_PAD + kq * 4);
        }
    };

    float bst[16];
    auto ldg_B = [&](int c) {
        #pragma unroll
        for (int i = 0; i < 4; ++i) {
            int idx = i * 256 + tid;
            int n = idx & 127, kq = idx >> 7;
            #pragma unroll
            for (int j = 0; j < 4; ++j) {
                int kg = c * BK + kq * 4 + j;
                float v = 0.0f;
                if (kg < 784) v = tf32_rn(__ldg(x + (size_t)kg * BATCH + bn0 + n));
                bst[i * 4 + j] = v;
            }
        }
    };
    auto sts_B = [&](int buf) {
        #pragma unroll
        for (int i = 0; i < 4; ++i) {
            int idx = i * 256 + tid;
            int n = idx & 127, kq = idx >> 7;
            sts128(bBase[buf] + (n * B_STRIDE + kq * 4) * 4,
                   bst[i * 4], bst[i * 4 + 1], bst[i * 4 + 2], bst[i * 4 + 3]);
        }
    };

    float acc[4][4][4];
    #pragma unroll
    for (int mt = 0; mt < 4; ++mt)
        #pragma unroll
        for (int nt = 0; nt < 4; ++nt)
            #pragma unroll
            for (int q = 0; q < 4; ++q) acc[mt][nt][q] = 0.0f;

    // prologue
    load_A(0, 0);
    ldg_B(0);
    sts_B(0);
    cp_async_wait_all();
    __syncthreads();

    const int g   = lane >> 3;           // ldmatrix address group
    const int sub = lane & 7;

    for (int c = 0; c < NCHUNK; ++c) {
        const int buf = c & 1;
        if (c + 1 < NCHUNK) {
            load_A(c + 1, buf ^ 1);
            ldg_B(c + 1);
        }

        // MMA over this chunk: 4 k-steps of 8
        #pragma unroll
        for (int ks = 0; ks < 4; ++ks) {
            uint32_t af[4][4], bf[4][2];
            #pragma unroll
            for (int mt = 0; mt < 4; ++mt) {
                int row = warp_m * 64 + mt * 16 + (g & 1) * 8 + sub;
                int kq  = ks * 2 + (g >> 1);
                int pk  = kq ^ (sub);             // row&7 == sub
                ldsm_x4(af[mt][0], af[mt][1], af[mt][2], af[mt][3],
                        aBase[buf] + row * 128 + pk * 16);
            }
            #pragma unroll
            for (int p = 0; p < 2; ++p) {
                int n  = warp_n * 32 + p * 16 + (g >> 1) * 8 + sub;
                int kq = ks * 2 + (g & 1);
                uint32_t r0, r1, r2, r3;
                ldsm_x4(r0, r1, r2, r3, bBase[buf] + (n * B_STRIDE + kq * 4) * 4);
                bf[2 * p][0] = r0; bf[2 * p][1] = r1;
                bf[2 * p + 1][0] = r2; bf[2 * p + 1][1] = r3;
            }
            #pragma unroll
            for (int mt = 0; mt < 4; ++mt)
                #pragma unroll
                for (int nt = 0; nt < 4; ++nt)
                    mma_tf32(acc[mt][nt], af[mt], bf[nt]);
        }

        if (c + 1 < NCHUNK) {
            sts_B(buf ^ 1);
            cp_async_wait_all();
        }
        __syncthreads();
    }

    // ---- epilogue: bias + relu + STG.64 ----
    #pragma unroll
    for (int mt = 0; mt < 4; ++mt) {
        int m0 = bm0 + warp_m * 64 + mt * 16 + (lane >> 2);
        int m1 = m0 + 8;
        float b0 = (m0 < 784) ? __ldg(bias + m0) : 0.0f;
        float b1 = (m1 < 784) ? __ldg(bias + m1) : 0.0f;
        #pragma unroll
        for (int nt = 0; nt < 4; ++nt) {
            int n = bn0 + warp_n * 32 + nt * 8 + (lane & 3) * 2;
            if (m0 < 784) {
                float2 v;
                v.x = fmaxf(acc[mt][nt][0] + b0, 0.0f);
                v.y = fmaxf(acc[mt][nt][1] + b0, 0.0f);
                *reinterpret_cast<float2*>(out + (size_t)m0 * BATCH + n) = v;
            }
            if (m1 < 784) {
                float2 v;
                v.x = fmaxf(acc[mt][nt][2] + b1, 0.0f);
                v.y = fmaxf(acc[mt][nt][3] + b1, 0.0f);
                *reinterpret_cast<float2*>(out + (size_t)m1 * BATCH + n) = v;
            }
        }
    }
}

// ---------------- launch ----------------
extern "C" void kernel_launch(void* const* d_in, const int* in_sizes, int n_in,
                              void* d_out, int out_size) {
    const float *x = nullptr, *W = nullptr, *B = nullptr;
    for (int i = 0; i < n_in; ++i) {
        if (in_sizes[i] > 1000000)      x = (const float*)d_in[i];
        else if (in_sizes[i] == 21952)  W = (const float*)d_in[i];
        else                            B = (const float*)d_in[i];
    }
    static int smem_set = 0;
    if (!smem_set) {
        cudaFuncSetAttribute(tnn_gemm_kernel,
                             cudaFuncAttributeMaxDynamicSharedMemorySize, SMEM_TOTAL);
        smem_set = 1;
    }
    build_A_kernel<<<2800, 256>>>(W);
    dim3 grid(BATCH / 128, 7);
    tnn_gemm_kernel<<<grid, 256, SMEM_TOTAL>>>((float*)d_out, x, B);
}

// round 4
// speedup vs baseline: 2.2980x; 2.2980x over previous
#include <cuda_runtime.h>
#include <cuda_bf16.h>
#include <cstdint>

// out[784,65536] = relu( bcirc(W)[784,784] @ x[784,65536] + bias )
// mma.sync.m16n8k8.tf32, CTA tile 128x128, BK=32, 8 warps (2m x 4n),
// 3-stage cp.async pipeline (distance 2) for both A and B.
// A: pre-rounded bcirc(W) in __device__ buffer, XOR-swizzled smem, ldmatrix.
// B: raw cp.async k-major [32][136-pad], fragment LDS.32 + cvt.rna.tf32.

#define BATCH   65536
#define K_PAD   800
#define BK      32
#define NCHUNK  25
#define NSTAGE  3

#define A_BUF    16384                   // 128 rows x 32 floats
#define B_STRIDE 136                     // floats per k-row (128 + 8 pad)
#define B_BUF    (BK * B_STRIDE * 4)     // 17408
#define STAGE    (A_BUF + B_BUF)         // 33792
#define SMEM_TOTAL (NSTAGE * STAGE)      // 101376

__device__ float g_A[896 * K_PAD];       // bcirc(W), tf32-rounded, zero-padded

// ---------------- helpers ----------------
__device__ __forceinline__ uint32_t smem_u32(const void* p) {
    uint32_t a;
    asm("{ .reg .u64 t; cvta.to.shared.u64 t, %1; cvt.u32.u64 %0, t; }" : "=r"(a) : "l"(p));
    return a;
}
__device__ __forceinline__ float tf32_rn(float v) {
    uint32_t o;
    asm("cvt.rna.tf32.f32 %0, %1;" : "=r"(o) : "r"(__float_as_uint(v)));
    return __uint_as_float(o);
}
__device__ __forceinline__ void cp_async16(uint32_t dst, const void* src) {
    asm volatile("cp.async.cg.shared.global [%0], [%1], 16;" :: "r"(dst), "l"(src));
}
__device__ __forceinline__ void cp_async16_zfill(uint32_t dst, const void* src, bool pred) {
    int sz = pred ? 16 : 0;
    asm volatile("cp.async.cg.shared.global [%0], [%1], 16, %2;"
                 :: "r"(dst), "l"(src), "r"(sz));
}
__device__ __forceinline__ void cp_commit() {
    asm volatile("cp.async.commit_group;" ::: "memory");
}
__device__ __forceinline__ void ldsm_x4(uint32_t& r0, uint32_t& r1, uint32_t& r2,
                                        uint32_t& r3, uint32_t addr) {
    asm volatile("ldmatrix.sync.aligned.m8n8.x4.shared.b16 {%0,%1,%2,%3}, [%4];"
                 : "=r"(r0), "=r"(r1), "=r"(r2), "=r"(r3) : "r"(addr));
}
__device__ __forceinline__ float lds32(uint32_t a) {
    float v;
    asm volatile("ld.shared.f32 %0, [%1];" : "=f"(v) : "r"(a));
    return v;
}
__device__ __forceinline__ void mma_tf32(float* c, const uint32_t* a, const uint32_t* b) {
    asm volatile(
        "mma.sync.aligned.m16n8k8.row.col.f32.tf32.tf32.f32 "
        "{%0,%1,%2,%3}, {%4,%5,%6,%7}, {%8,%9}, {%0,%1,%2,%3};"
        : "+f"(c[0]), "+f"(c[1]), "+f"(c[2]), "+f"(c[3])
        : "r"(a[0]), "r"(a[1]), "r"(a[2]), "r"(a[3]), "r"(b[0]), "r"(b[1]));
}

// ---------------- prep: bcirc(W), tf32-rounded, zero-padded ----------------
__global__ void build_A_kernel(const float* __restrict__ W) {
    int idx = blockIdx.x * 256 + threadIdx.x;
    if (idx >= 896 * K_PAD) return;
    int r = idx / K_PAD, k = idx - r * K_PAD;
    float v = 0.0f;
    if (r < 784 && k < 784) {
        int ko = r / 28, m = r % 28, j = k / 28, n = k % 28;
        int l = ko - j; if (l < 0) l += 28;
        v = tf32_rn(W[l * 784 + m * 28 + n]);
    }
    g_A[idx] = v;
}

// ---------------- main GEMM ----------------
__global__ void __launch_bounds__(256, 2)
tnn_gemm_kernel(float* __restrict__ out, const float* __restrict__ x,
                const float* __restrict__ bias) {
    extern __shared__ char smem[];
    const uint32_t sb = smem_u32(smem);

    const int tid    = threadIdx.x;
    const int lane   = tid & 31;
    const int wid    = tid >> 5;
    const int warp_m = wid & 1;          // rows 0 / 64
    const int warp_n = wid >> 1;         // cols 0/32/64/96
    const int bn0    = blockIdx.x * 128;
    const int bm0    = blockIdx.y * 128;

    // producer: issue one stage (A tile + B tile) and commit a group
    auto issue_stage = [&](int c, int s) {
        const uint32_t ab = sb + s * STAGE;
        const uint32_t bb = ab + A_BUF;
        const float* asrc = g_A + (size_t)bm0 * K_PAD + c * BK;
        #pragma unroll
        for (int i = 0; i < 4; ++i) {
            int idx = i * 256 + tid;
            int row = idx >> 3, kq = idx & 7;
            int pk  = kq ^ (row & 7);
            cp_async16(ab + row * 128 + pk * 16, asrc + (size_t)row * K_PAD + kq * 4);
        }
        #pragma unroll
        for (int i = 0; i < 4; ++i) {
            int idx  = i * 256 + tid;
            int krow = idx >> 5, n4 = idx & 31;
            int kg   = c * BK + krow;
            cp_async16_zfill(bb + (krow * B_STRIDE + n4 * 4) * 4,
                             x + (size_t)kg * BATCH + bn0 + n4 * 4, kg < 784);
        }
        cp_commit();
    };

    float acc[4][4][4];
    #pragma unroll
    for (int mt = 0; mt < 4; ++mt)
        #pragma unroll
        for (int nt = 0; nt < 4; ++nt)
            #pragma unroll
            for (int q = 0; q < 4; ++q) acc[mt][nt][q] = 0.0f;

    issue_stage(0, 0);
    issue_stage(1, 1);

    const int g   = lane >> 3;   // A ldsm address group
    const int sub = lane & 7;
    const int tig = lane & 3;    // B fragment: k row within group of 4
    const int gid = lane >> 2;   // B fragment: n col within 8-tile

    for (int c = 0; c < NCHUNK; ++c) {
        if (c == NCHUNK - 1) asm volatile("cp.async.wait_group 0;" ::: "memory");
        else                 asm volatile("cp.async.wait_group 1;" ::: "memory");
        __syncthreads();

        const uint32_t ab = sb + (c % NSTAGE) * STAGE;
        const uint32_t bb = ab + A_BUF;

        #pragma unroll
        for (int ks = 0; ks < 4; ++ks) {
            uint32_t af[4][4];
            #pragma unroll
            for (int mt = 0; mt < 4; ++mt) {
                int row = warp_m * 64 + mt * 16 + (g & 1) * 8 + sub;
                int kq  = ks * 2 + (g >> 1);
                int pk  = kq ^ sub;          // row & 7 == sub
                ldsm_x4(af[mt][0], af[mt][1], af[mt][2], af[mt][3],
                        ab + row * 128 + pk * 16);
            }
            #pragma unroll
            for (int nt = 0; nt < 4; ++nt) {
                int coln = warp_n * 32 + nt * 8 + gid;
                uint32_t a0 = bb + ((ks * 8 + tig) * B_STRIDE + coln) * 4;
                uint32_t bf[2];
                bf[0] = __float_as_uint(tf32_rn(lds32(a0)));
                bf[1] = __float_as_uint(tf32_rn(lds32(a0 + 4 * B_STRIDE * 4)));
                #pragma unroll
                for (int mt = 0; mt < 4; ++mt)
                    mma_tf32(acc[mt][nt], af[mt], bf);
            }
        }

        if (c + 2 < NCHUNK) issue_stage(c + 2, (c + 2) % NSTAGE);
    }

    // ---- epilogue: bias + relu + STG.64 ----
    #pragma unroll
    for (int mt = 0; mt < 4; ++mt) {
        int m0 = bm0 + warp_m * 64 + mt * 16 + (lane >> 2);
        int m1 = m0 + 8;
        float b0 = (m0 < 784) ? __ldg(bias + m0) : 0.0f;
        float b1 = (m1 < 784) ? __ldg(bias + m1) : 0.0f;
        #pragma unroll
        for (int nt = 0; nt < 4; ++nt) {
            int n = bn0 + warp_n * 32 + nt * 8 + (lane & 3) * 2;
            if (m0 < 784) {
                float2 v;
                v.x = fmaxf(acc[mt][nt][0] + b0, 0.0f);
                v.y = fmaxf(acc[mt][nt][1] + b0, 0.0f);
                *reinterpret_cast<float2*>(out + (size_t)m0 * BATCH + n) = v;
            }
            if (m1 < 784) {
                float2 v;
                v.x = fmaxf(acc[mt][nt][2] + b1, 0.0f);
                v.y = fmaxf(acc[mt][nt][3] + b1, 0.0f);
                *reinterpret_cast<float2*>(out + (size_t)m1 * BATCH + n) = v;
            }
        }
    }
}

// ---------------- launch ----------------
extern "C" void kernel_launch(void* const* d_in, const int* in_sizes, int n_in,
                              void* d_out, int out_size) {
    const float *x = nullptr, *W = nullptr, *B = nullptr;
    for (int i = 0; i < n_in; ++i) {
        if (in_sizes[i] > 1000000)      x = (const float*)d_in[i];
        else if (in_sizes[i] == 21952)  W = (const float*)d_in[i];
        else                            B = (const float*)d_in[i];
    }
    cudaFuncSetAttribute(tnn_gemm_kernel,
                         cudaFuncAttributeMaxDynamicSharedMemorySize, SMEM_TOTAL);
    build_A_kernel<<<2800, 256>>>(W);
    dim3 grid(BATCH / 128, 7);
    tnn_gemm_kernel<<<grid, 256, SMEM_TOTAL>>>((float*)d_out, x, B);
}

// round 5
// speedup vs baseline: 3.4631x; 1.5070x over previous
#include <cuda_runtime.h>
#include <cuda_fp16.h>
#include <cstdint>

// out[784,65536] = relu( bcirc(W)[784,784] @ x[784,65536] + bias )
// mma.sync.m16n8k16.f16 (fp32 accum). CTA tile 128x128, BK=32, 8 warps (2m x 4n),
// 4-stage cp.async pipeline (distance 3).
// A: half bcirc(W) in __device__ buf, 128B-super-row XOR swizzle, ldmatrix b16.
// B: raw f32 cp.async k-major [32][132-pad], fragment LDS.32 + cvt.rn.f16x2.f32.

#define BATCH   65536
#define K_PAD   800
#define BK      32
#define NCHUNK  25
#define NSTAGE  4

#define A_BUF    8192                    // 64 super-rows x 128 B (128 rows x 32 half)
#define B_STRIDE 132                     // floats per k-row (128 + 4 pad)
#define B_BUF    (BK * B_STRIDE * 4)     // 16896
#define STAGE    (A_BUF + B_BUF)         // 25088
#define SMEM_TOTAL (NSTAGE * STAGE)      // 100352

__device__ __half g_Ah[896 * K_PAD];     // bcirc(W) in half, zero-padded

// ---------------- helpers ----------------
__device__ __forceinline__ uint32_t smem_u32(const void* p) {
    uint32_t a;
    asm("{ .reg .u64 t; cvta.to.shared.u64 t, %1; cvt.u32.u64 %0, t; }" : "=r"(a) : "l"(p));
    return a;
}
__device__ __forceinline__ void cp_async16(uint32_t dst, const void* src) {
    asm volatile("cp.async.cg.shared.global [%0], [%1], 16;" :: "r"(dst), "l"(src));
}
__device__ __forceinline__ void cp_async16_zfill(uint32_t dst, const void* src, bool pred) {
    int sz = pred ? 16 : 0;
    asm volatile("cp.async.cg.shared.global [%0], [%1], 16, %2;"
                 :: "r"(dst), "l"(src), "r"(sz));
}
__device__ __forceinline__ void cp_commit() {
    asm volatile("cp.async.commit_group;" ::: "memory");
}
__device__ __forceinline__ void ldsm_x4(uint32_t& r0, uint32_t& r1, uint32_t& r2,
                                        uint32_t& r3, uint32_t addr) {
    asm volatile("ldmatrix.sync.aligned.m8n8.x4.shared.b16 {%0,%1,%2,%3}, [%4];"
                 : "=r"(r0), "=r"(r1), "=r"(r2), "=r"(r3) : "r"(addr));
}
__device__ __forceinline__ float lds32(uint32_t a) {
    float v;
    asm volatile("ld.shared.f32 %0, [%1];" : "=f"(v) : "r"(a));
    return v;
}
__device__ __forceinline__ uint32_t pack_f16x2(float lo, float hi) {
    uint32_t r;
    asm("cvt.rn.f16x2.f32 %0, %1, %2;" : "=r"(r) : "f"(hi), "f"(lo));
    return r;
}
__device__ __forceinline__ void mma_f16(float* c, const uint32_t* a, const uint32_t* b) {
    asm volatile(
        "mma.sync.aligned.m16n8k16.row.col.f32.f16.f16.f32 "
        "{%0,%1,%2,%3}, {%4,%5,%6,%7}, {%8,%9}, {%0,%1,%2,%3};"
        : "+f"(c[0]), "+f"(c[1]), "+f"(c[2]), "+f"(c[3])
        : "r"(a[0]), "r"(a[1]), "r"(a[2]), "r"(a[3]), "r"(b[0]), "r"(b[1]));
}

// ---------------- prep: bcirc(W) -> half, zero-padded ----------------
__global__ void build_A_kernel(const float* __restrict__ W) {
    int idx = blockIdx.x * 256 + threadIdx.x;
    if (idx >= 896 * K_PAD) return;
    int r = idx / K_PAD, k = idx - r * K_PAD;
    float v = 0.0f;
    if (r < 784 && k < 784) {
        int ko = r / 28, m = r % 28, j = k / 28, n = k % 28;
        int l = ko - j; if (l < 0) l += 28;
        v = W[l * 784 + m * 28 + n];
    }
    g_Ah[idx] = __float2half_rn(v);
}

// ---------------- main GEMM ----------------
__global__ void __launch_bounds__(256, 2)
tnn_gemm_kernel(float* __restrict__ out, const float* __restrict__ x,
                const float* __restrict__ bias) {
    extern __shared__ char smem[];
    const uint32_t sb = smem_u32(smem);

    const int tid    = threadIdx.x;
    const int lane   = tid & 31;
    const int wid    = tid >> 5;
    const int warp_m = wid & 1;          // rows 0 / 64
    const int warp_n = wid >> 1;         // cols 0/32/64/96
    const int bm0    = blockIdx.x * 128; // m-tile (0..6) -- x-dim for L2 reuse of x
    const int bn0    = blockIdx.y * 128; // batch strip

    // producer: one stage (A half tile + B f32 tile), one commit group
    auto issue_stage = [&](int c, int s) {
        const uint32_t ab = sb + s * STAGE;
        const uint32_t bb = ab + A_BUF;
        const __half* asrc = g_Ah + (size_t)bm0 * K_PAD + c * BK;
        #pragma unroll
        for (int i = 0; i < 2; ++i) {                 // A: 512 x 16B chunks
            int idx = i * 256 + tid;
            int row = idx >> 2, kc = idx & 3;         // kc: 8-half chunk within row
            int sr = row >> 1, h = row & 1;
            int chunk = (h * 4 + kc) ^ (sr & 3);
            cp_async16(ab + sr * 128 + chunk * 16,
                       asrc + (size_t)row * K_PAD + kc * 8);
        }
        #pragma unroll
        for (int i = 0; i < 4; ++i) {                 // B: 1024 x 16B chunks
            int idx  = i * 256 + tid;
            int krow = idx >> 5, n4 = idx & 31;
            int kg   = c * BK + krow;
            cp_async16_zfill(bb + (krow * B_STRIDE + n4 * 4) * 4,
                             x + (size_t)kg * BATCH + bn0 + n4 * 4, kg < 784);
        }
        cp_commit();
    };

    float acc[4][4][4];
    #pragma unroll
    for (int mt = 0; mt < 4; ++mt)
        #pragma unroll
        for (int nt = 0; nt < 4; ++nt)
            #pragma unroll
            for (int q = 0; q < 4; ++q) acc[mt][nt][q] = 0.0f;

    issue_stage(0, 0);
    issue_stage(1, 1);
    issue_stage(2, 2);

    // A ldmatrix lane mapping (m16n8k16 fragment from 4 x m8n8 b16 matrices)
    const int m8     = lane >> 3;
    const int rowoff = (lane & 7) + (m8 & 1) * 8;
    const int kcsel  = m8 >> 1;              // 0: k 0-7, 1: k 8-15 within fragment
    // B fragment lane mapping
    const int tb  = lane & 3;                // k pair index
    const int gid = lane >> 2;               // n within 8

    for (int c = 0; c < NCHUNK; ++c) {
        if (c < NCHUNK - 3)      asm volatile("cp.async.wait_group 2;" ::: "memory");
        else if (c == NCHUNK - 3) asm volatile("cp.async.wait_group 2;" ::: "memory");
        else if (c == NCHUNK - 2) asm volatile("cp.async.wait_group 1;" ::: "memory");
        else                      asm volatile("cp.async.wait_group 0;" ::: "memory");
        __syncthreads();

        const uint32_t ab = sb + (c % NSTAGE) * STAGE;
        const uint32_t bb = ab + A_BUF;

        #pragma unroll
        for (int ks = 0; ks < 2; ++ks) {             // 2 k-steps of 16
            uint32_t af[4][4];
            #pragma unroll
            for (int mt = 0; mt < 4; ++mt) {
                int row = warp_m * 64 + mt * 16 + rowoff;
                int sr = row >> 1, h = row & 1;
                int kc = ks * 2 + kcsel;
                int chunk = (h * 4 + kc) ^ (sr & 3);
                ldsm_x4(af[mt][0], af[mt][1], af[mt][2], af[mt][3],
                        ab + sr * 128 + chunk * 16);
            }
            #pragma unroll
            for (int nt = 0; nt < 4; ++nt) {
                int coln = warp_n * 32 + nt * 8 + gid;
                int k0 = ks * 16 + tb * 2;
                uint32_t base = bb + (k0 * B_STRIDE + coln) * 4;
                uint32_t bf[2];
                bf[0] = pack_f16x2(lds32(base),
                                   lds32(base + B_STRIDE * 4));
                bf[1] = pack_f16x2(lds32(base + 8 * B_STRIDE * 4),
                                   lds32(base + 9 * B_STRIDE * 4));
                #pragma unroll
                for (int mt = 0; mt < 4; ++mt)
                    mma_f16(acc[mt][nt], af[mt], bf);
            }
        }

        if (c + 3 < NCHUNK) issue_stage(c + 3, (c + 3) % NSTAGE);
    }

    // ---- epilogue: bias + relu + STG.64 ----
    #pragma unroll
    for (int mt = 0; mt < 4; ++mt) {
        int m0 = bm0 + warp_m * 64 + mt * 16 + (lane >> 2);
        int m1 = m0 + 8;
        float b0 = (m0 < 784) ? __ldg(bias + m0) : 0.0f;
        float b1 = (m1 < 784) ? __ldg(bias + m1) : 0.0f;
        #pragma unroll
        for (int nt = 0; nt < 4; ++nt) {
            int n = bn0 + warp_n * 32 + nt * 8 + (lane & 3) * 2;
            if (m0 < 784) {
                float2 v;
                v.x = fmaxf(acc[mt][nt][0] + b0, 0.0f);
                v.y = fmaxf(acc[mt][nt][1] + b0, 0.0f);
                *reinterpret_cast<float2*>(out + (size_t)m0 * BATCH + n) = v;
            }
            if (m1 < 784) {
                float2 v;
                v.x = fmaxf(acc[mt][nt][2] + b1, 0.0f);
                v.y = fmaxf(acc[mt][nt][3] + b1, 0.0f);
                *reinterpret_cast<float2*>(out + (size_t)m1 * BATCH + n) = v;
            }
        }
    }
}

// ---------------- launch ----------------
extern "C" void kernel_launch(void* const* d_in, const int* in_sizes, int n_in,
                              void* d_out, int out_size) {
    const float *x = nullptr, *W = nullptr, *B = nullptr;
    for (int i = 0; i < n_in; ++i) {
        if (in_sizes[i] > 1000000)      x = (const float*)d_in[i];
        else if (in_sizes[i] == 21952)  W = (const float*)d_in[i];
        else                            B = (const float*)d_in[i];
    }
    cudaFuncSetAttribute(tnn_gemm_kernel,
                         cudaFuncAttributeMaxDynamicSharedMemorySize, SMEM_TOTAL);
    build_A_kernel<<<2800, 256>>>(W);
    dim3 grid(7, BATCH / 128);   // x = m-tile (co-resident m's share x strip in L2)
    tnn_gemm_kernel<<<grid, 256, SMEM_TOTAL>>>((float*)d_out, x, B);
}

// round 6
// speedup vs baseline: 3.5318x; 1.0198x over previous
#include <cuda_runtime.h>
#include <cuda_fp16.h>
#include <cstdint>

// out[784,65536] = relu( bcirc(W)[784,784] @ x[784,65536] + bias )
// mma.sync.m16n8k16.f16 (fp32 accum). CTA tile 128x128, BK=32, 8 warps (2m x 4n),
// 5-stage cp.async pipeline (distance 4).
// A: half bcirc(W), XOR-swizzled smem, ldmatrix.x4.
// B: x pre-converted to half in gmem; k-major [32][136] smem (272B row stride,
//    ldmatrix-conflict-free); fragments via ldmatrix.x4.trans.

#define BATCH   65536
#define K_PAD   800
#define BK      32
#define NCHUNK  25
#define NSTAGE  5

#define A_BUF    8192                    // 64 super-rows x 128 B (128 rows x 32 half)
#define B_STRH   136                     // halfs per k-row (128 + 8 pad) = 272 B
#define B_BUF    (BK * B_STRH * 2)       // 8704
#define STAGE    (A_BUF + B_BUF)         // 16896
#define SMEM_TOTAL (NSTAGE * STAGE)      // 84480

__device__ __half g_Ah[896 * K_PAD];             // bcirc(W) half, zero-padded
__device__ __half g_xh[784ULL * BATCH];          // x in half (103 MB)

// ---------------- helpers ----------------
__device__ __forceinline__ uint32_t smem_u32(const void* p) {
    uint32_t a;
    asm("{ .reg .u64 t; cvta.to.shared.u64 t, %1; cvt.u32.u64 %0, t; }" : "=r"(a) : "l"(p));
    return a;
}
__device__ __forceinline__ void cp_async16(uint32_t dst, const void* src) {
    asm volatile("cp.async.cg.shared.global [%0], [%1], 16;" :: "r"(dst), "l"(src));
}
__device__ __forceinline__ void cp_async16_zfill(uint32_t dst, const void* src, bool pred) {
    int sz = pred ? 16 : 0;
    asm volatile("cp.async.cg.shared.global [%0], [%1], 16, %2;"
                 :: "r"(dst), "l"(src), "r"(sz));
}
__device__ __forceinline__ void cp_commit() {
    asm volatile("cp.async.commit_group;" ::: "memory");
}
__device__ __forceinline__ void ldsm_x4(uint32_t& r0, uint32_t& r1, uint32_t& r2,
                                        uint32_t& r3, uint32_t addr) {
    asm volatile("ldmatrix.sync.aligned.m8n8.x4.shared.b16 {%0,%1,%2,%3}, [%4];"
                 : "=r"(r0), "=r"(r1), "=r"(r2), "=r"(r3) : "r"(addr));
}
__device__ __forceinline__ void ldsm_x4_trans(uint32_t& r0, uint32_t& r1, uint32_t& r2,
                                              uint32_t& r3, uint32_t addr) {
    asm volatile("ldmatrix.sync.aligned.m8n8.x4.trans.shared.b16 {%0,%1,%2,%3}, [%4];"
                 : "=r"(r0), "=r"(r1), "=r"(r2), "=r"(r3) : "r"(addr));
}
__device__ __forceinline__ void mma_f16(float* c, const uint32_t* a, const uint32_t* b) {
    asm volatile(
        "mma.sync.aligned.m16n8k16.row.col.f32.f16.f16.f32 "
        "{%0,%1,%2,%3}, {%4,%5,%6,%7}, {%8,%9}, {%0,%1,%2,%3};"
        : "+f"(c[0]), "+f"(c[1]), "+f"(c[2]), "+f"(c[3])
        : "r"(a[0]), "r"(a[1]), "r"(a[2]), "r"(a[3]), "r"(b[0]), "r"(b[1]));
}

// ---------------- prep kernels ----------------
__global__ void build_A_kernel(const float* __restrict__ W) {
    int idx = blockIdx.x * 256 + threadIdx.x;
    if (idx >= 896 * K_PAD) return;
    int r = idx / K_PAD, k = idx - r * K_PAD;
    float v = 0.0f;
    if (r < 784 && k < 784) {
        int ko = r / 28, m = r % 28, j = k / 28, n = k % 28;
        int l = ko - j; if (l < 0) l += 28;
        v = W[l * 784 + m * 28 + n];
    }
    g_Ah[idx] = __float2half_rn(v);
}

__global__ void conv_x_kernel(const float* __restrict__ x) {
    size_t i = ((size_t)blockIdx.x * 256 + threadIdx.x) * 4;
    float4 v = __ldg((const float4*)(x + i));
    __half2* dst = (__half2*)(g_xh + i);
    dst[0] = __floats2half2_rn(v.x, v.y);
    dst[1] = __floats2half2_rn(v.z, v.w);
}

// ---------------- main GEMM ----------------
__global__ void __launch_bounds__(256, 2)
tnn_gemm_kernel(float* __restrict__ out, const float* __restrict__ bias) {
    extern __shared__ char smem[];
    const uint32_t sb = smem_u32(smem);

    const int tid    = threadIdx.x;
    const int lane   = tid & 31;
    const int wid    = tid >> 5;
    const int warp_m = wid & 1;          // rows 0 / 64
    const int warp_n = wid >> 1;         // cols 0/32/64/96
    const int bm0    = blockIdx.x * 128; // m-tile (0..6)
    const int bn0    = blockIdx.y * 128; // batch strip

    // producer: one stage (A half tile + B half tile), one commit group
    auto issue_stage = [&](int c, int s) {
        const uint32_t ab = sb + s * STAGE;
        const uint32_t bb = ab + A_BUF;
        const __half* asrc = g_Ah + (size_t)bm0 * K_PAD + c * BK;
        #pragma unroll
        for (int i = 0; i < 2; ++i) {                 // A: 512 x 16B
            int idx = i * 256 + tid;
            int row = idx >> 2, kc = idx & 3;
            int sr = row >> 1, h = row & 1;
            int chunk = (h * 4 + kc) ^ (sr & 3);
            cp_async16(ab + sr * 128 + chunk * 16,
                       asrc + (size_t)row * K_PAD + kc * 8);
        }
        #pragma unroll
        for (int i = 0; i < 2; ++i) {                 // B: 512 x 16B
            int idx  = i * 256 + tid;
            int krow = idx >> 4, c16 = idx & 15;
            int kg   = c * BK + krow;
            cp_async16_zfill(bb + krow * (B_STRH * 2) + c16 * 16,
                             g_xh + (size_t)kg * BATCH + bn0 + c16 * 8, kg < 784);
        }
        cp_commit();
    };

    float acc[4][4][4];
    #pragma unroll
    for (int mt = 0; mt < 4; ++mt)
        #pragma unroll
        for (int nt = 0; nt < 4; ++nt)
            #pragma unroll
            for (int q = 0; q < 4; ++q) acc[mt][nt][q] = 0.0f;

    issue_stage(0, 0);
    issue_stage(1, 1);
    issue_stage(2, 2);
    issue_stage(3, 3);

    // A ldmatrix lane mapping
    const int m8     = lane >> 3;
    const int rowoff = (lane & 7) + (m8 & 1) * 8;
    const int kcsel  = m8 >> 1;
    // B ldmatrix.trans lane mapping: matrix q = lane>>3 -> k-half (q&1), n-sub (q>>1)
    const int bq  = lane >> 3;
    const int bkr = lane & 7;
    const int b_krow_off = (bq & 1) * 8 + bkr;       // k within 16-step
    const int b_n_off    = (bq >> 1) * 8;            // n-sub within 16

    for (int c = 0; c < NCHUNK; ++c) {
        if (c < NCHUNK - 3)       asm volatile("cp.async.wait_group 3;" ::: "memory");
        else if (c == NCHUNK - 3) asm volatile("cp.async.wait_group 2;" ::: "memory");
        else if (c == NCHUNK - 2) asm volatile("cp.async.wait_group 1;" ::: "memory");
        else                      asm volatile("cp.async.wait_group 0;" ::: "memory");
        __syncthreads();

        const uint32_t ab = sb + (c % NSTAGE) * STAGE;
        const uint32_t bb = ab + A_BUF;

        #pragma unroll
        for (int ks = 0; ks < 2; ++ks) {             // 2 k-steps of 16
            uint32_t af[4][4];
            #pragma unroll
            for (int mt = 0; mt < 4; ++mt) {
                int row = warp_m * 64 + mt * 16 + rowoff;
                int sr = row >> 1, h = row & 1;
                int kc = ks * 2 + kcsel;
                int chunk = (h * 4 + kc) ^ (sr & 3);
                ldsm_x4(af[mt][0], af[mt][1], af[mt][2], af[mt][3],
                        ab + sr * 128 + chunk * 16);
            }
            uint32_t bf[4][2];
            #pragma unroll
            for (int p = 0; p < 2; ++p) {            // n-pairs (nt 0,1) and (2,3)
                int k = ks * 16 + b_krow_off;
                int n = warp_n * 32 + p * 16 + b_n_off;
                uint32_t r0, r1, r2, r3;
                ldsm_x4_trans(r0, r1, r2, r3, bb + (k * B_STRH + n) * 2);
                bf[2 * p][0] = r0;     bf[2 * p][1] = r1;
                bf[2 * p + 1][0] = r2; bf[2 * p + 1][1] = r3;
            }
            #pragma unroll
            for (int nt = 0; nt < 4; ++nt)
                #pragma unroll
                for (int mt = 0; mt < 4; ++mt)
                    mma_f16(acc[mt][nt], af[mt], bf[nt]);
        }

        if (c + 4 < NCHUNK) issue_stage(c + 4, (c + 4) % NSTAGE);
    }

    // ---- epilogue: bias + relu + STG.64 ----
    #pragma unroll
    for (int mt = 0; mt < 4; ++mt) {
        int m0 = bm0 + warp_m * 64 + mt * 16 + (lane >> 2);
        int m1 = m0 + 8;
        float b0 = (m0 < 784) ? __ldg(bias + m0) : 0.0f;
        float b1 = (m1 < 784) ? __ldg(bias + m1) : 0.0f;
        #pragma unroll
        for (int nt = 0; nt < 4; ++nt) {
            int n = bn0 + warp_n * 32 + nt * 8 + (lane & 3) * 2;
            if (m0 < 784) {
                float2 v;
                v.x = fmaxf(acc[mt][nt][0] + b0, 0.0f);
                v.y = fmaxf(acc[mt][nt][1] + b0, 0.0f);
                *reinterpret_cast<float2*>(out + (size_t)m0 * BATCH + n) = v;
            }
            if (m1 < 784) {
                float2 v;
                v.x = fmaxf(acc[mt][nt][2] + b1, 0.0f);
                v.y = fmaxf(acc[mt][nt][3] + b1, 0.0f);
                *reinterpret_cast<float2*>(out + (size_t)m1 * BATCH + n) = v;
            }
        }
    }
}

// ---------------- launch ----------------
extern "C" void kernel_launch(void* const* d_in, const int* in_sizes, int n_in,
                              void* d_out, int out_size) {
    const float *x = nullptr, *W = nullptr, *B = nullptr;
    for (int i = 0; i < n_in; ++i) {
        if (in_sizes[i] > 1000000)      x = (const float*)d_in[i];
        else if (in_sizes[i] == 21952)  W = (const float*)d_in[i];
        else                            B = (const float*)d_in[i];
    }
    cudaFuncSetAttribute(tnn_gemm_kernel,
                         cudaFuncAttributeMaxDynamicSharedMemorySize, SMEM_TOTAL);
    build_A_kernel<<<2800, 256>>>(W);
    conv_x_kernel<<<(784 * BATCH / 4) / 256, 256>>>(x);
    dim3 grid(7, BATCH / 128);
    tnn_gemm_kernel<<<grid, 256, SMEM_TOTAL>>>((float*)d_out, B);
}

// round 7
// speedup vs baseline: 3.7148x; 1.0518x over previous
#include <cuda_runtime.h>
#include <cuda_fp16.h>
#include <cstdint>

// out[784,65536] = relu( bcirc(W)[784,784] @ x[784,65536] + bias )
// mma.sync.m16n8k16.f16 (fp32 accum). CTA tile 128x128, BK=64, 8 warps (2m x 4n),
// 3-stage cp.async pipeline (distance 2), producer issued before MMA block.
// A: half bcirc(W) (K padded to 832), 128B-row XOR swizzle, ldmatrix.x4.
// B: x pre-converted to half in gmem; k-major [64][136] smem; ldmatrix.x4.trans.

#define BATCH   65536
#define K_PAD   832
#define BK      64
#define NCHUNK  13
#define NSTAGE  3

#define A_BUF    16384                   // 128 rows x 128 B (64 half per row)
#define B_STRH   136                     // halfs per k-row (128 + 8 pad) = 272 B
#define B_BUF    (BK * B_STRH * 2)       // 17408
#define STAGE    (A_BUF + B_BUF)         // 33792
#define SMEM_TOTAL (NSTAGE * STAGE)      // 101376

__device__ __half g_Ah[896 * K_PAD];             // bcirc(W) half, zero-padded
__device__ __half g_xh[784ULL * BATCH];          // x in half (103 MB)

// ---------------- helpers ----------------
__device__ __forceinline__ uint32_t smem_u32(const void* p) {
    uint32_t a;
    asm("{ .reg .u64 t; cvta.to.shared.u64 t, %1; cvt.u32.u64 %0, t; }" : "=r"(a) : "l"(p));
    return a;
}
__device__ __forceinline__ void cp_async16(uint32_t dst, const void* src) {
    asm volatile("cp.async.cg.shared.global [%0], [%1], 16;" :: "r"(dst), "l"(src));
}
__device__ __forceinline__ void cp_async16_zfill(uint32_t dst, const void* src, bool pred) {
    int sz = pred ? 16 : 0;
    asm volatile("cp.async.cg.shared.global [%0], [%1], 16, %2;"
                 :: "r"(dst), "l"(src), "r"(sz));
}
__device__ __forceinline__ void cp_commit() {
    asm volatile("cp.async.commit_group;" ::: "memory");
}
__device__ __forceinline__ void ldsm_x4(uint32_t& r0, uint32_t& r1, uint32_t& r2,
                                        uint32_t& r3, uint32_t addr) {
    asm volatile("ldmatrix.sync.aligned.m8n8.x4.shared.b16 {%0,%1,%2,%3}, [%4];"
                 : "=r"(r0), "=r"(r1), "=r"(r2), "=r"(r3) : "r"(addr));
}
__device__ __forceinline__ void ldsm_x4_trans(uint32_t& r0, uint32_t& r1, uint32_t& r2,
                                              uint32_t& r3, uint32_t addr) {
    asm volatile("ldmatrix.sync.aligned.m8n8.x4.trans.shared.b16 {%0,%1,%2,%3}, [%4];"
                 : "=r"(r0), "=r"(r1), "=r"(r2), "=r"(r3) : "r"(addr));
}
__device__ __forceinline__ void mma_f16(float* c, const uint32_t* a, const uint32_t* b) {
    asm volatile(
        "mma.sync.aligned.m16n8k16.row.col.f32.f16.f16.f32 "
        "{%0,%1,%2,%3}, {%4,%5,%6,%7}, {%8,%9}, {%0,%1,%2,%3};"
        : "+f"(c[0]), "+f"(c[1]), "+f"(c[2]), "+f"(c[3])
        : "r"(a[0]), "r"(a[1]), "r"(a[2]), "r"(a[3]), "r"(b[0]), "r"(b[1]));
}

// ---------------- prep kernels ----------------
__global__ void build_A_kernel(const float* __restrict__ W) {
    int idx = blockIdx.x * 256 + threadIdx.x;
    if (idx >= 896 * K_PAD) return;
    int r = idx / K_PAD, k = idx - r * K_PAD;
    float v = 0.0f;
    if (r < 784 && k < 784) {
        int ko = r / 28, m = r % 28, j = k / 28, n = k % 28;
        int l = ko - j; if (l < 0) l += 28;
        v = W[l * 784 + m * 28 + n];
    }
    g_Ah[idx] = __float2half_rn(v);
}

__global__ void conv_x_kernel(const float* __restrict__ x) {
    size_t i = ((size_t)blockIdx.x * 256 + threadIdx.x) * 4;
    float4 v = __ldg((const float4*)(x + i));
    __half2* dst = (__half2*)(g_xh + i);
    dst[0] = __floats2half2_rn(v.x, v.y);
    dst[1] = __floats2half2_rn(v.z, v.w);
}

// ---------------- main GEMM ----------------
__global__ void __launch_bounds__(256, 2)
tnn_gemm_kernel(float* __restrict__ out, const float* __restrict__ bias) {
    extern __shared__ char smem[];
    const uint32_t sb = smem_u32(smem);

    const int tid    = threadIdx.x;
    const int lane   = tid & 31;
    const int wid    = tid >> 5;
    const int warp_m = wid & 1;          // rows 0 / 64
    const int warp_n = wid >> 1;         // cols 0/32/64/96
    const int bm0    = blockIdx.x * 128; // m-tile (0..6)
    const int bn0    = blockIdx.y * 128; // batch strip

    // producer: one stage (A 128x64 half + B 64x128 half), one commit group
    auto issue_stage = [&](int c, int s) {
        const uint32_t ab = sb + s * STAGE;
        const uint32_t bb = ab + A_BUF;
        const __half* asrc = g_Ah + (size_t)bm0 * K_PAD + c * BK;
        #pragma unroll
        for (int i = 0; i < 4; ++i) {                 // A: 1024 x 16B
            int idx = i * 256 + tid;
            int row = idx >> 3, kc = idx & 7;
            int chunk = kc ^ (row & 7);
            cp_async16(ab + row * 128 + chunk * 16,
                       asrc + (size_t)row * K_PAD + kc * 8);
        }
        #pragma unroll
        for (int i = 0; i < 4; ++i) {                 // B: 1024 x 16B
            int idx  = i * 256 + tid;
            int krow = idx >> 4, c16 = idx & 15;
            int kg   = c * BK + krow;
            cp_async16_zfill(bb + krow * (B_STRH * 2) + c16 * 16,
                             g_xh + (size_t)kg * BATCH + bn0 + c16 * 8, kg < 784);
        }
        cp_commit();
    };

    float acc[4][4][4];
    #pragma unroll
    for (int mt = 0; mt < 4; ++mt)
        #pragma unroll
        for (int nt = 0; nt < 4; ++nt)
            #pragma unroll
            for (int q = 0; q < 4; ++q) acc[mt][nt][q] = 0.0f;

    issue_stage(0, 0);
    issue_stage(1, 1);

    // A ldmatrix lane mapping
    const int m8     = lane >> 3;
    const int rowoff = (lane & 7) + (m8 & 1) * 8;
    const int kcsel  = m8 >> 1;              // 16B chunk within 32B k-step pair
    // B ldmatrix.trans lane mapping
    const int bq  = lane >> 3;
    const int b_krow_off = (bq & 1) * 8 + (lane & 7);
    const int b_n_off    = (bq >> 1) * 8;

    for (int c = 0; c < NCHUNK; ++c) {
        if (c == NCHUNK - 1) asm volatile("cp.async.wait_group 0;" ::: "memory");
        else                 asm volatile("cp.async.wait_group 1;" ::: "memory");
        __syncthreads();

        if (c + 2 < NCHUNK) issue_stage(c + 2, (c + 2) % NSTAGE);

        const uint32_t ab = sb + (c % NSTAGE) * STAGE;
        const uint32_t bb = ab + A_BUF;

        #pragma unroll
        for (int ks = 0; ks < 4; ++ks) {             // 4 k-steps of 16
            uint32_t af[4][4];
            #pragma unroll
            for (int mt = 0; mt < 4; ++mt) {
                int row = warp_m * 64 + mt * 16 + rowoff;
                int kc  = ks * 2 + kcsel;
                int chunk = kc ^ (row & 7);
                ldsm_x4(af[mt][0], af[mt][1], af[mt][2], af[mt][3],
                        ab + row * 128 + chunk * 16);
            }
            uint32_t bf[4][2];
            #pragma unroll
            for (int p = 0; p < 2; ++p) {
                int k = ks * 16 + b_krow_off;
                int n = warp_n * 32 + p * 16 + b_n_off;
                uint32_t r0, r1, r2, r3;
                ldsm_x4_trans(r0, r1, r2, r3, bb + (k * B_STRH + n) * 2);
                bf[2 * p][0] = r0;     bf[2 * p][1] = r1;
                bf[2 * p + 1][0] = r2; bf[2 * p + 1][1] = r3;
            }
            #pragma unroll
            for (int nt = 0; nt < 4; ++nt)
                #pragma unroll
                for (int mt = 0; mt < 4; ++mt)
                    mma_f16(acc[mt][nt], af[mt], bf[nt]);
        }
    }

    // ---- epilogue: bias + relu + STG.64 ----
    #pragma unroll
    for (int mt = 0; mt < 4; ++mt) {
        int m0 = bm0 + warp_m * 64 + mt * 16 + (lane >> 2);
        int m1 = m0 + 8;
        float b0 = (m0 < 784) ? __ldg(bias + m0) : 0.0f;
        float b1 = (m1 < 784) ? __ldg(bias + m1) : 0.0f;
        #pragma unroll
        for (int nt = 0; nt < 4; ++nt) {
            int n = bn0 + warp_n * 32 + nt * 8 + (lane & 3) * 2;
            if (m0 < 784) {
                float2 v;
                v.x = fmaxf(acc[mt][nt][0] + b0, 0.0f);
                v.y = fmaxf(acc[mt][nt][1] + b0, 0.0f);
                *reinterpret_cast<float2*>(out + (size_t)m0 * BATCH + n) = v;
            }
            if (m1 < 784) {
                float2 v;
                v.x = fmaxf(acc[mt][nt][2] + b1, 0.0f);
                v.y = fmaxf(acc[mt][nt][3] + b1, 0.0f);
                *reinterpret_cast<float2*>(out + (size_t)m1 * BATCH + n) = v;
            }
        }
    }
}

// ---------------- launch ----------------
extern "C" void kernel_launch(void* const* d_in, const int* in_sizes, int n_in,
                              void* d_out, int out_size) {
    const float *x = nullptr, *W = nullptr, *B = nullptr;
    for (int i = 0; i < n_in; ++i) {
        if (in_sizes[i] > 1000000)      x = (const float*)d_in[i];
        else if (in_sizes[i] == 21952)  W = (const float*)d_in[i];
        else                            B = (const float*)d_in[i];
    }
    cudaFuncSetAttribute(tnn_gemm_kernel,
                         cudaFuncAttributeMaxDynamicSharedMemorySize, SMEM_TOTAL);
    build_A_kernel<<<(896 * K_PAD + 255) / 256, 256>>>(W);
    conv_x_kernel<<<(784 * BATCH / 4) / 256, 256>>>(x);
    dim3 grid(7, BATCH / 128);
    tnn_gemm_kernel<<<grid, 256, SMEM_TOTAL>>>((float*)d_out, B);
}